// round 9
// baseline (speedup 1.0000x reference)
#include <cuda_runtime.h>
#include <cuda_fp16.h>
#include <cstdint>

#define BB   256
#define TT   2048
#define FIN  9
#define T1   1024
#define TPP  512
#define NN   131072
#define EE   2097152
#define HID  64
#define TW   260
#define PREP_BLOCKS 128

// ---------------- scratch (static device globals; no runtime alloc) ----------
__device__ int      d_cnt[NN];
__device__ int      d_ptr[NN];
__device__ int      d_cur[NN];
__device__ int      d_bsum[PREP_BLOCKS];
__device__ int      d_srow[EE];
__device__ float    d_dinv[NN];
__device__ float    d_h1[(size_t)BB * 16 * T1];   // conv1 output, CHANNEL-MAJOR [b][c][t]
__device__ __align__(16) __half d_g16[(size_t)NN * 32];    // layer-1 gather input (fp16)
__device__ __align__(16) __half d_gB16[(size_t)NN * HID];  // layer-2 gather input (fp16)
__device__ float    d_hB[(size_t)NN * HID];       // layer-2 output (fp32, pool input)
__device__ unsigned g_cnt;                        // grid barrier counter (memset per launch)

// ---------------- streams/events for capture fork/join ----------------------
static cudaStream_t g_s2;
static cudaEvent_t  g_ev0, g_evScat;
static void*        g_cnt_addr;
namespace {
struct StreamInit {
    StreamInit() {
        cudaStreamCreateWithFlags(&g_s2, cudaStreamNonBlocking);
        cudaEventCreateWithFlags(&g_ev0,    cudaEventDisableTiming);
        cudaEventCreateWithFlags(&g_evScat, cudaEventDisableTiming);
        cudaGetSymbolAddress(&g_cnt_addr, g_cnt);
    }
} g_streamInit;
}

// ---------------- grid barrier (single-wave, monotonic counter) --------------
__device__ __forceinline__ void gridbar(unsigned& phase) {
    __syncthreads();
    if (threadIdx.x == 0) {
        __threadfence();
        atomicAdd(&g_cnt, 1u);
        unsigned target = (++phase) * gridDim.x;
        while (atomicAdd(&g_cnt, 0u) < target) __nanosleep(64);
        __threadfence();
    }
    __syncthreads();
}

// ---------------- fused graph prep: zero+hist+scan+finalize+scatter ----------
__global__ void __launch_bounds__(1024)
prep_kernel(const int* __restrict__ row, const int* __restrict__ col) {
    __shared__ int s[1024];
    __shared__ int sb[PREP_BLOCKS];
    int tid = threadIdx.x, bid = blockIdx.x;
    int i = bid * 1024 + tid;
    unsigned phase = 0;

    d_cnt[i] = 0;
    gridbar(phase);

    #pragma unroll
    for (int j = 0; j < EE / NN; j++)
        atomicAdd(&d_cnt[col[i + j * NN]], 1);
    gridbar(phase);

    int v = d_cnt[i];
    s[tid] = v;
    __syncthreads();
    #pragma unroll
    for (int off = 1; off < 1024; off <<= 1) {
        int t = (tid >= off) ? s[tid - off] : 0;
        __syncthreads();
        s[tid] += t;
        __syncthreads();
    }
    int le = s[tid] - v;
    if (tid == 1023) d_bsum[bid] = s[1023];
    gridbar(phase);

    if (tid < PREP_BLOCKS) sb[tid] = d_bsum[tid];
    __syncthreads();
    #pragma unroll
    for (int off = 1; off < PREP_BLOCKS; off <<= 1) {
        int t = (tid < PREP_BLOCKS && tid >= off) ? sb[tid - off] : 0;
        __syncthreads();
        if (tid < PREP_BLOCKS) sb[tid] += t;
        __syncthreads();
    }
    int bex = (bid == 0) ? 0 : sb[bid - 1];

    int p = le + bex;
    d_ptr[i] = p;
    d_cur[i] = p;
    d_dinv[i] = rsqrtf((float)v + 1.0f);
    gridbar(phase);

    #pragma unroll
    for (int j = 0; j < EE / NN; j++) {
        int e = i + j * NN;
        int c = col[e];
        int q = atomicAdd(&d_cur[c], 1);
        d_srow[q] = row[e];
    }
}

// ---------------- conv1: (B,T,9) -> relu -> pool2 -> d_h1 [b][c][t] ----------
__global__ void conv1_kernel(const float* __restrict__ x,
                             const float* __restrict__ w,
                             const float* __restrict__ bias) {
    __shared__ __align__(16) float xs[TW * 9];
    __shared__ __align__(16) float ws[720];
    __shared__ float bs[16];
    int b = blockIdx.y, tp0 = blockIdx.x * 128, tid = threadIdx.x;

    for (int j = tid; j < 720; j += 128) {
        int c = j & 15, r = j >> 4, f = r / 5, k = r - f * 5;
        ws[j] = w[c * 45 + f * 5 + k];
    }
    if (tid < 16) bs[tid] = bias[tid];

    int base = 2 * tp0 - 2;
    const float* xb = x + (size_t)b * TT * FIN;
    for (int j = tid; j < TW * 9; j += 128) {
        int t = base + j / 9, f = j - (j / 9) * 9;
        xs[j] = (t >= 0 && t < TT) ? xb[t * 9 + f] : 0.0f;
    }
    __syncthreads();

    float s0[16], s1[16];
    #pragma unroll
    for (int c = 0; c < 16; c++) { s0[c] = 0.f; s1[c] = 0.f; }

    #pragma unroll
    for (int f = 0; f < 9; f++) {
        float v[6];
        #pragma unroll
        for (int j = 0; j < 6; j++) v[j] = xs[(2 * tid + j) * 9 + f];
        #pragma unroll
        for (int k = 0; k < 5; k++) {
            const float4* wr = (const float4*)&ws[(f * 5 + k) * 16];
            float a = v[k], bb = v[k + 1];
            #pragma unroll
            for (int q = 0; q < 4; q++) {
                float4 w4 = wr[q];
                s0[q*4+0] += w4.x * a;  s1[q*4+0] += w4.x * bb;
                s0[q*4+1] += w4.y * a;  s1[q*4+1] += w4.y * bb;
                s0[q*4+2] += w4.z * a;  s1[q*4+2] += w4.z * bb;
                s0[q*4+3] += w4.w * a;  s1[q*4+3] += w4.w * bb;
            }
        }
    }

    float* hb = d_h1 + (size_t)b * 16 * T1 + tp0 + tid;
    #pragma unroll
    for (int c = 0; c < 16; c++)
        hb[c * T1] = fmaxf(fmaxf(s0[c], s1[c]) + bs[c], 0.f);
}

// ------- conv2 (register-blocked): d_h1 [b][c][t] -> g16 = fp16(dinv*h2) ----
__global__ void conv2_kernel(const float* __restrict__ w2,
                             const float* __restrict__ b2) {
    __shared__ __align__(16) float buf[16 * TW];
    __shared__ __align__(16) float ws[2560];
    __shared__ float bs[32];
    int b = blockIdx.y, tid = threadIdx.x;
    int cg = tid & 7, pg = tid >> 3;
    int t0 = blockIdx.x * 256;

    for (int j = tid; j < 2560; j += 128) {
        int c = j & 31, r = j >> 5;
        ws[j] = w2[c * 80 + r];
    }
    if (tid < 32) bs[tid] = b2[tid];

    int base = t0 - 2;
    const float* hb = d_h1 + (size_t)b * 16 * T1;
    #pragma unroll
    for (int ci = 0; ci < 16; ci++)
        for (int j = tid; j < TW; j += 128) {
            int t = base + j;
            buf[ci * TW + j] = (t >= 0 && t < T1) ? hb[ci * T1 + t] : 0.f;
        }
    __syncthreads();

    float acc[64];
    #pragma unroll
    for (int o = 0; o < 64; o++) acc[o] = 0.f;

    #pragma unroll 2
    for (int ci = 0; ci < 16; ci++) {
        float v[20];
        const float4* vp = (const float4*)(buf + ci * TW + pg * 16);
        #pragma unroll
        for (int q = 0; q < 5; q++) {
            float4 t4 = vp[q];
            v[q*4+0] = t4.x; v[q*4+1] = t4.y; v[q*4+2] = t4.z; v[q*4+3] = t4.w;
        }
        #pragma unroll
        for (int k = 0; k < 5; k++) {
            float4 w4 = *(const float4*)&ws[(ci * 5 + k) * 32 + cg * 4];
            #pragma unroll
            for (int p = 0; p < 16; p++) {
                float a = v[p + k];
                acc[p*4+0] += a * w4.x;
                acc[p*4+1] += a * w4.y;
                acc[p*4+2] += a * w4.z;
                acc[p*4+3] += a * w4.w;
            }
        }
    }

    int nbase = b * TPP + (t0 >> 1) + pg * 8;
    #pragma unroll
    for (int pp = 0; pp < 8; pp++) {
        int n = nbase + pp;
        float dv = d_dinv[n];
        int pa = pp * 2 * 4, pb = pa + 4;
        float c0 = fmaxf(fmaxf(acc[pa+0], acc[pb+0]) + bs[cg*4+0], 0.f) * dv;
        float c1 = fmaxf(fmaxf(acc[pa+1], acc[pb+1]) + bs[cg*4+1], 0.f) * dv;
        float c2 = fmaxf(fmaxf(acc[pa+2], acc[pb+2]) + bs[cg*4+2], 0.f) * dv;
        float c3 = fmaxf(fmaxf(acc[pa+3], acc[pb+3]) + bs[cg*4+3], 0.f) * dv;
        __half2* o = (__half2*)(d_g16 + (size_t)n * 32 + cg * 4);
        o[0] = __floats2half2_rn(c0, c1);
        o[1] = __floats2half2_rn(c2, c3);
    }
}

// ------- fused layer 1: 4 nodes/warp, batched-idx gather + GEMM 32->64 ------
__global__ void gcn1_fused_kernel(const float* __restrict__ w,
                                  const float* __restrict__ bias) {
    __shared__ __align__(16) float ws[2048];     // W1 [c][o], 32x64
    __shared__ float bs[64];
    int tid = threadIdx.x;
    for (int j = tid; j < 2048; j += 256) ws[j] = w[j];
    if (tid < 64) bs[tid] = bias[tid];
    __syncthreads();

    int warp = tid >> 5, lane = tid & 31;
    int n0 = (blockIdx.x * 8 + warp) * 4;        // nodes n0..n0+3
    int4 p4 = *(const int4*)&d_ptr[n0];
    int4 c4 = *(const int4*)&d_cnt[n0];
    int p[4] = {p4.x, p4.y, p4.z, p4.w};
    int cnt[4] = {c4.x, c4.y, c4.z, c4.w};

    // self loops (4 independent 64B row loads, lane = channel)
    float acc[4];
    #pragma unroll
    for (int k = 0; k < 4; k++)
        acc[k] = __half2float(d_g16[(size_t)(n0 + k) * 32 + lane]);

    int maxc = max(max(cnt[0], cnt[1]), max(cnt[2], cnt[3]));
    for (int base = 0; base < maxc; base += 32) {
        int idx[4];
        #pragma unroll
        for (int k = 0; k < 4; k++)
            idx[k] = (base + lane < cnt[k]) ? d_srow[p[k] + base + lane] : 0;
        int mlim = min(maxc - base, 32);
        for (int i = 0; i < mlim; i++) {
            #pragma unroll
            for (int k = 0; k < 4; k++) {
                int r = __shfl_sync(0xffffffffu, idx[k], i);
                if (base + i < cnt[k])
                    acc[k] += __half2float(d_g16[(size_t)r * 32 + lane]);
            }
        }
    }

    // epilogue GEMM via shfl broadcast (lane -> channels 2*lane, 2*lane+1)
    #pragma unroll
    for (int k = 0; k < 4; k++) {
        float s0 = 0.f, s1 = 0.f;
        #pragma unroll
        for (int c = 0; c < 32; c++) {
            float v = __shfl_sync(0xffffffffu, acc[k], c);
            s0 += v * ws[c * 64 + 2 * lane];
            s1 += v * ws[c * 64 + 2 * lane + 1];
        }
        float dv = d_dinv[n0 + k];
        float o0 = fmaxf(dv * s0 + bs[2 * lane],     0.f) * dv;
        float o1 = fmaxf(dv * s1 + bs[2 * lane + 1], 0.f) * dv;
        ((__half2*)d_gB16)[(size_t)(n0 + k) * 32 + lane] = __floats2half2_rn(o0, o1);
    }
}

// ------- fused layer 2: 4 nodes/warp, batched-idx gather + GEMM 64->64 ------
__global__ void gcn2_fused_kernel(const float* __restrict__ w,
                                  const float* __restrict__ bias) {
    __shared__ __align__(16) float ws[4096];     // W2 [c][o], 64x64
    __shared__ float bs[64];
    int tid = threadIdx.x;
    for (int j = tid; j < 4096; j += 256) ws[j] = w[j];
    if (tid < 64) bs[tid] = bias[tid];
    __syncthreads();

    int warp = tid >> 5, lane = tid & 31;
    int n0 = (blockIdx.x * 8 + warp) * 4;
    int4 p4 = *(const int4*)&d_ptr[n0];
    int4 c4 = *(const int4*)&d_cnt[n0];
    int p[4] = {p4.x, p4.y, p4.z, p4.w};
    int cnt[4] = {c4.x, c4.y, c4.z, c4.w};
    const __half2* g = (const __half2*)d_gB16;

    // self loops (lane = channel pair)
    float2 acc[4];
    #pragma unroll
    for (int k = 0; k < 4; k++)
        acc[k] = __half22float2(g[(size_t)(n0 + k) * 32 + lane]);

    int maxc = max(max(cnt[0], cnt[1]), max(cnt[2], cnt[3]));
    for (int base = 0; base < maxc; base += 32) {
        int idx[4];
        #pragma unroll
        for (int k = 0; k < 4; k++)
            idx[k] = (base + lane < cnt[k]) ? d_srow[p[k] + base + lane] : 0;
        int mlim = min(maxc - base, 32);
        for (int i = 0; i < mlim; i++) {
            #pragma unroll
            for (int k = 0; k < 4; k++) {
                int r = __shfl_sync(0xffffffffu, idx[k], i);
                if (base + i < cnt[k]) {
                    float2 v = __half22float2(g[(size_t)r * 32 + lane]);
                    acc[k].x += v.x;
                    acc[k].y += v.y;
                }
            }
        }
    }

    // epilogue GEMM via shfl broadcast (lane j holds channels 2j, 2j+1)
    #pragma unroll
    for (int k = 0; k < 4; k++) {
        float s0 = 0.f, s1 = 0.f;
        #pragma unroll
        for (int j = 0; j < 32; j++) {
            float va = __shfl_sync(0xffffffffu, acc[k].x, j);   // channel 2j
            float vb = __shfl_sync(0xffffffffu, acc[k].y, j);   // channel 2j+1
            s0 += va * ws[(2*j) * 64 + 2 * lane] + vb * ws[(2*j+1) * 64 + 2 * lane];
            s1 += va * ws[(2*j) * 64 + 2 * lane + 1] + vb * ws[(2*j+1) * 64 + 2 * lane + 1];
        }
        float dv = d_dinv[n0 + k];
        float2 o;
        o.x = fmaxf(dv * s0 + bs[2 * lane],     0.f);
        o.y = fmaxf(dv * s1 + bs[2 * lane + 1], 0.f);
        ((float2*)d_hB)[(size_t)(n0 + k) * 32 + lane] = o;
    }
}

// ---------------- mean pool over TP + FC ------------------------------------
__global__ void pool_fc_kernel(const float* __restrict__ fcw,
                               const float* __restrict__ fcb,
                               float* __restrict__ out) {
    __shared__ float m[4][64];
    int b = blockIdx.x, tid = threadIdx.x;
    int f = tid & 63, q = tid >> 6;
    const float* hb = d_hB + (size_t)b * TPP * 64;
    float s = 0.f;
    for (int tp = q; tp < TPP; tp += 4) s += hb[tp * 64 + f];
    m[q][f] = s;
    __syncthreads();
    if (tid < 64) {
        float tot = (m[0][tid] + m[1][tid]) + (m[2][tid] + m[3][tid]);
        m[0][tid] = tot * (1.0f / TPP);
    }
    __syncthreads();
    if (tid < 6) {
        float acc = fcb[tid];
        #pragma unroll
        for (int k = 0; k < 64; k++) acc += m[0][k] * fcw[tid * 64 + k];
        out[b * 6 + tid] = acc;
    }
}

// ---------------- launch -----------------------------------------------------
extern "C" void kernel_launch(void* const* d_in, const int* in_sizes, int n_in,
                              void* d_out, int out_size) {
    const float* x   = (const float*)d_in[0];
    const int*   ei  = (const int*)  d_in[1];
    const float* w1  = (const float*)d_in[2];
    const float* b1  = (const float*)d_in[3];
    const float* w2  = (const float*)d_in[4];
    const float* b2  = (const float*)d_in[5];
    const float* g1w = (const float*)d_in[6];
    const float* g1b = (const float*)d_in[7];
    const float* g2w = (const float*)d_in[8];
    const float* g2b = (const float*)d_in[9];
    const float* fcw = (const float*)d_in[10];
    const float* fcb = (const float*)d_in[11];
    float* out = (float*)d_out;

    // fork: single fused prep kernel on side stream
    cudaEventRecord(g_ev0, 0);
    cudaStreamWaitEvent(g_s2, g_ev0, 0);
    cudaMemsetAsync(g_cnt_addr, 0, sizeof(unsigned), g_s2);
    prep_kernel<<<PREP_BLOCKS, 1024, 0, g_s2>>>(ei, ei + EE);
    cudaEventRecord(g_evScat, g_s2);

    // main stream: conv1 overlaps prep
    conv1_kernel<<<dim3(8, BB), 128>>>(x, w1, b1);
    cudaStreamWaitEvent(0, g_evScat, 0);          // conv2 needs dinv; gathers need CSR
    conv2_kernel<<<dim3(4, BB), 128>>>(w2, b2);

    // fused GCN layers (4 nodes/warp, batched-index gathers)
    gcn1_fused_kernel<<<NN / 32, 256>>>(g1w, g1b);
    gcn2_fused_kernel<<<NN / 32, 256>>>(g2w, g2b);

    // pool + fc
    pool_fc_kernel<<<BB, 256>>>(fcw, fcb, out);
}

// round 10
// speedup vs baseline: 1.7443x; 1.7443x over previous
#include <cuda_runtime.h>
#include <cuda_fp16.h>
#include <cstdint>

#define BB   256
#define TT   2048
#define FIN  9
#define T1   1024
#define TPP  512
#define NN   131072
#define EE   2097152
#define HID  64
#define TW   260
#define PREP_BLOCKS 128

// ---------------- scratch (static device globals; no runtime alloc) ----------
__device__ int      d_cnt[NN];
__device__ int      d_ptr[NN];
__device__ int      d_cur[NN];
__device__ int      d_bsum[PREP_BLOCKS];
__device__ int      d_srow[EE];
__device__ float    d_dinv[NN];
__device__ float    d_h1[(size_t)BB * 16 * T1];   // conv1 output, CHANNEL-MAJOR [b][c][t]
__device__ __align__(16) __half d_g16[(size_t)NN * 32];    // layer-1 gather input (fp16)
__device__ __align__(16) __half d_gB16[(size_t)NN * HID];  // layer-2 gather input (fp16)
__device__ float    d_hB[(size_t)NN * HID];       // layer-2 output (fp32, pool input)
__device__ unsigned g_cnt;                        // grid barrier counter (memset per launch)

// ---------------- streams/events for capture fork/join ----------------------
static cudaStream_t g_s2;
static cudaEvent_t  g_ev0, g_evScat;
static void*        g_cnt_addr;
namespace {
struct StreamInit {
    StreamInit() {
        cudaStreamCreateWithFlags(&g_s2, cudaStreamNonBlocking);
        cudaEventCreateWithFlags(&g_ev0,    cudaEventDisableTiming);
        cudaEventCreateWithFlags(&g_evScat, cudaEventDisableTiming);
        cudaGetSymbolAddress(&g_cnt_addr, g_cnt);
    }
} g_streamInit;
}

// ---------------- grid barrier (single-wave, monotonic counter) --------------
__device__ __forceinline__ void gridbar(unsigned& phase) {
    __syncthreads();
    if (threadIdx.x == 0) {
        __threadfence();
        atomicAdd(&g_cnt, 1u);
        unsigned target = (++phase) * gridDim.x;
        while (atomicAdd(&g_cnt, 0u) < target) __nanosleep(64);
        __threadfence();
    }
    __syncthreads();
}

// ---------------- fused graph prep: zero+hist+scan+finalize+scatter ----------
__global__ void __launch_bounds__(1024)
prep_kernel(const int* __restrict__ row, const int* __restrict__ col) {
    __shared__ int s[1024];
    __shared__ int sb[PREP_BLOCKS];
    int tid = threadIdx.x, bid = blockIdx.x;
    int i = bid * 1024 + tid;
    unsigned phase = 0;

    d_cnt[i] = 0;
    gridbar(phase);

    #pragma unroll
    for (int j = 0; j < EE / NN; j++)
        atomicAdd(&d_cnt[col[i + j * NN]], 1);
    gridbar(phase);

    int v = d_cnt[i];
    s[tid] = v;
    __syncthreads();
    #pragma unroll
    for (int off = 1; off < 1024; off <<= 1) {
        int t = (tid >= off) ? s[tid - off] : 0;
        __syncthreads();
        s[tid] += t;
        __syncthreads();
    }
    int le = s[tid] - v;
    if (tid == 1023) d_bsum[bid] = s[1023];
    gridbar(phase);

    if (tid < PREP_BLOCKS) sb[tid] = d_bsum[tid];
    __syncthreads();
    #pragma unroll
    for (int off = 1; off < PREP_BLOCKS; off <<= 1) {
        int t = (tid < PREP_BLOCKS && tid >= off) ? sb[tid - off] : 0;
        __syncthreads();
        if (tid < PREP_BLOCKS) sb[tid] += t;
        __syncthreads();
    }
    int bex = (bid == 0) ? 0 : sb[bid - 1];

    int p = le + bex;
    d_ptr[i] = p;
    d_cur[i] = p;
    d_dinv[i] = rsqrtf((float)v + 1.0f);
    gridbar(phase);

    #pragma unroll
    for (int j = 0; j < EE / NN; j++) {
        int e = i + j * NN;
        int c = col[e];
        int q = atomicAdd(&d_cur[c], 1);
        d_srow[q] = row[e];
    }
}

// ---------------- conv1: (B,T,9) -> relu -> pool2 -> d_h1 [b][c][t] ----------
__global__ void conv1_kernel(const float* __restrict__ x,
                             const float* __restrict__ w,
                             const float* __restrict__ bias) {
    __shared__ __align__(16) float xs[TW * 9];
    __shared__ __align__(16) float ws[720];
    __shared__ float bs[16];
    int b = blockIdx.y, tp0 = blockIdx.x * 128, tid = threadIdx.x;

    for (int j = tid; j < 720; j += 128) {
        int c = j & 15, r = j >> 4, f = r / 5, k = r - f * 5;
        ws[j] = w[c * 45 + f * 5 + k];
    }
    if (tid < 16) bs[tid] = bias[tid];

    int base = 2 * tp0 - 2;
    const float* xb = x + (size_t)b * TT * FIN;
    for (int j = tid; j < TW * 9; j += 128) {
        int t = base + j / 9, f = j - (j / 9) * 9;
        xs[j] = (t >= 0 && t < TT) ? xb[t * 9 + f] : 0.0f;
    }
    __syncthreads();

    float s0[16], s1[16];
    #pragma unroll
    for (int c = 0; c < 16; c++) { s0[c] = 0.f; s1[c] = 0.f; }

    #pragma unroll
    for (int f = 0; f < 9; f++) {
        float v[6];
        #pragma unroll
        for (int j = 0; j < 6; j++) v[j] = xs[(2 * tid + j) * 9 + f];
        #pragma unroll
        for (int k = 0; k < 5; k++) {
            const float4* wr = (const float4*)&ws[(f * 5 + k) * 16];
            float a = v[k], bb = v[k + 1];
            #pragma unroll
            for (int q = 0; q < 4; q++) {
                float4 w4 = wr[q];
                s0[q*4+0] += w4.x * a;  s1[q*4+0] += w4.x * bb;
                s0[q*4+1] += w4.y * a;  s1[q*4+1] += w4.y * bb;
                s0[q*4+2] += w4.z * a;  s1[q*4+2] += w4.z * bb;
                s0[q*4+3] += w4.w * a;  s1[q*4+3] += w4.w * bb;
            }
        }
    }

    float* hb = d_h1 + (size_t)b * 16 * T1 + tp0 + tid;
    #pragma unroll
    for (int c = 0; c < 16; c++)
        hb[c * T1] = fmaxf(fmaxf(s0[c], s1[c]) + bs[c], 0.f);
}

// ------- conv2 (register-blocked): d_h1 [b][c][t] -> g16 = fp16(dinv*h2) ----
__global__ void conv2_kernel(const float* __restrict__ w2,
                             const float* __restrict__ b2) {
    __shared__ __align__(16) float buf[16 * TW];
    __shared__ __align__(16) float ws[2560];
    __shared__ float bs[32];
    int b = blockIdx.y, tid = threadIdx.x;
    int cg = tid & 7, pg = tid >> 3;
    int t0 = blockIdx.x * 256;

    for (int j = tid; j < 2560; j += 128) {
        int c = j & 31, r = j >> 5;
        ws[j] = w2[c * 80 + r];
    }
    if (tid < 32) bs[tid] = b2[tid];

    int base = t0 - 2;
    const float* hb = d_h1 + (size_t)b * 16 * T1;
    #pragma unroll
    for (int ci = 0; ci < 16; ci++)
        for (int j = tid; j < TW; j += 128) {
            int t = base + j;
            buf[ci * TW + j] = (t >= 0 && t < T1) ? hb[ci * T1 + t] : 0.f;
        }
    __syncthreads();

    float acc[64];
    #pragma unroll
    for (int o = 0; o < 64; o++) acc[o] = 0.f;

    #pragma unroll 2
    for (int ci = 0; ci < 16; ci++) {
        float v[20];
        const float4* vp = (const float4*)(buf + ci * TW + pg * 16);
        #pragma unroll
        for (int q = 0; q < 5; q++) {
            float4 t4 = vp[q];
            v[q*4+0] = t4.x; v[q*4+1] = t4.y; v[q*4+2] = t4.z; v[q*4+3] = t4.w;
        }
        #pragma unroll
        for (int k = 0; k < 5; k++) {
            float4 w4 = *(const float4*)&ws[(ci * 5 + k) * 32 + cg * 4];
            #pragma unroll
            for (int p = 0; p < 16; p++) {
                float a = v[p + k];
                acc[p*4+0] += a * w4.x;
                acc[p*4+1] += a * w4.y;
                acc[p*4+2] += a * w4.z;
                acc[p*4+3] += a * w4.w;
            }
        }
    }

    int nbase = b * TPP + (t0 >> 1) + pg * 8;
    #pragma unroll
    for (int pp = 0; pp < 8; pp++) {
        int n = nbase + pp;
        float dv = d_dinv[n];
        int pa = pp * 2 * 4, pb = pa + 4;
        float c0 = fmaxf(fmaxf(acc[pa+0], acc[pb+0]) + bs[cg*4+0], 0.f) * dv;
        float c1 = fmaxf(fmaxf(acc[pa+1], acc[pb+1]) + bs[cg*4+1], 0.f) * dv;
        float c2 = fmaxf(fmaxf(acc[pa+2], acc[pb+2]) + bs[cg*4+2], 0.f) * dv;
        float c3 = fmaxf(fmaxf(acc[pa+3], acc[pb+3]) + bs[cg*4+3], 0.f) * dv;
        __half2* o = (__half2*)(d_g16 + (size_t)n * 32 + cg * 4);
        o[0] = __floats2half2_rn(c0, c1);
        o[1] = __floats2half2_rn(c2, c3);
    }
}

// ------- fused layer 1: 2 nodes/warp (half-warp each) + GEMM 32->64 ---------
// Row = 32ch fp16 = 64B = 16 lanes x half2. 32-bit index math throughout.
__global__ void gcn1_fused_kernel(const float* __restrict__ w,
                                  const float* __restrict__ bias) {
    __shared__ __align__(16) float ws[2048];     // W1 [c][o], 32x64
    __shared__ float bs[64];
    __shared__ float st[8][64];                  // per-warp: 2 nodes x 32 ch
    int tid = threadIdx.x;
    for (int j = tid; j < 2048; j += 256) ws[j] = w[j];
    if (tid < 64) bs[tid] = bias[tid];
    __syncthreads();

    int warp = tid >> 5, lane = tid & 31;
    int half = lane >> 4, hl = lane & 15;        // half-warp id, lane-in-half
    int nbase = (blockIdx.x * 8 + warp) * 2;
    int n = nbase + half;                        // this half-warp's node
    int p = d_ptr[n];
    int cnt = d_cnt[n];
    const __half2* gp = (const __half2*)d_g16 + hl;   // +r*16 selects row r

    // self loop
    float2 acc = __half22float2(gp[n << 4]);

    int e = 0;
    for (; e + 8 <= cnt; e += 8) {
        int r0 = d_srow[p+e],   r1 = d_srow[p+e+1], r2 = d_srow[p+e+2], r3 = d_srow[p+e+3];
        int r4 = d_srow[p+e+4], r5 = d_srow[p+e+5], r6 = d_srow[p+e+6], r7 = d_srow[p+e+7];
        float2 v0 = __half22float2(gp[r0 << 4]);
        float2 v1 = __half22float2(gp[r1 << 4]);
        float2 v2 = __half22float2(gp[r2 << 4]);
        float2 v3 = __half22float2(gp[r3 << 4]);
        float2 v4 = __half22float2(gp[r4 << 4]);
        float2 v5 = __half22float2(gp[r5 << 4]);
        float2 v6 = __half22float2(gp[r6 << 4]);
        float2 v7 = __half22float2(gp[r7 << 4]);
        acc.x += ((v0.x + v1.x) + (v2.x + v3.x)) + ((v4.x + v5.x) + (v6.x + v7.x));
        acc.y += ((v0.y + v1.y) + (v2.y + v3.y)) + ((v4.y + v5.y) + (v6.y + v7.y));
    }
    for (; e < cnt; e++) {
        int r = d_srow[p + e];
        float2 v = __half22float2(gp[r << 4]);
        acc.x += v.x; acc.y += v.y;
    }

    st[warp][half * 32 + 2 * hl]     = acc.x;
    st[warp][half * 32 + 2 * hl + 1] = acc.y;
    __syncwarp();

    // epilogue: both nodes, full warp; lane -> channels 2*lane, 2*lane+1
    #pragma unroll
    for (int k = 0; k < 2; k++) {
        int nk = nbase + k;
        float s0 = 0.f, s1 = 0.f;
        #pragma unroll
        for (int c = 0; c < 32; c++) {
            float v = st[warp][k * 32 + c];
            float2 wp = ((const float2*)&ws[c * 64])[lane];   // LDS.64
            s0 += v * wp.x;
            s1 += v * wp.y;
        }
        float dv = d_dinv[nk];
        float o0 = fmaxf(dv * s0 + bs[2 * lane],     0.f) * dv;
        float o1 = fmaxf(dv * s1 + bs[2 * lane + 1], 0.f) * dv;
        ((__half2*)d_gB16)[(nk << 5) + lane] = __floats2half2_rn(o0, o1);
    }
}

// ------- fused layer 2: 1 node/warp gather (half2/lane) + GEMM 64->64 -------
__global__ void gcn2_fused_kernel(const float* __restrict__ w,
                                  const float* __restrict__ bias) {
    __shared__ __align__(16) float ws[4096];     // W2 [c][o], 64x64
    __shared__ float bs[64];
    __shared__ float st[8][64];
    int tid = threadIdx.x;
    for (int j = tid; j < 4096; j += 256) ws[j] = w[j];
    if (tid < 64) bs[tid] = bias[tid];
    __syncthreads();

    int warp = tid >> 5, lane = tid & 31;
    int gw = blockIdx.x * 8 + warp;
    int p = d_ptr[gw];
    int cnt = d_cnt[gw];
    const __half2* gp = (const __half2*)d_gB16 + lane;   // +r*32 selects row r

    // self loop
    float2 acc = __half22float2(gp[gw << 5]);

    int e = 0;
    for (; e + 8 <= cnt; e += 8) {
        int r0 = d_srow[p+e],   r1 = d_srow[p+e+1], r2 = d_srow[p+e+2], r3 = d_srow[p+e+3];
        int r4 = d_srow[p+e+4], r5 = d_srow[p+e+5], r6 = d_srow[p+e+6], r7 = d_srow[p+e+7];
        float2 v0 = __half22float2(gp[r0 << 5]);
        float2 v1 = __half22float2(gp[r1 << 5]);
        float2 v2 = __half22float2(gp[r2 << 5]);
        float2 v3 = __half22float2(gp[r3 << 5]);
        float2 v4 = __half22float2(gp[r4 << 5]);
        float2 v5 = __half22float2(gp[r5 << 5]);
        float2 v6 = __half22float2(gp[r6 << 5]);
        float2 v7 = __half22float2(gp[r7 << 5]);
        acc.x += ((v0.x + v1.x) + (v2.x + v3.x)) + ((v4.x + v5.x) + (v6.x + v7.x));
        acc.y += ((v0.y + v1.y) + (v2.y + v3.y)) + ((v4.y + v5.y) + (v6.y + v7.y));
    }
    for (; e < cnt; e++) {
        int r = d_srow[p + e];
        float2 v = __half22float2(gp[r << 5]);
        acc.x += v.x; acc.y += v.y;
    }

    st[warp][2 * lane]     = acc.x;
    st[warp][2 * lane + 1] = acc.y;
    __syncwarp();

    // epilogue: lane -> channels 2*lane, 2*lane+1
    float s0 = 0.f, s1 = 0.f;
    #pragma unroll
    for (int c = 0; c < 64; c++) {
        float v = st[warp][c];
        float2 wp = ((const float2*)&ws[c * 64])[lane];   // LDS.64
        s0 += v * wp.x;
        s1 += v * wp.y;
    }
    float dv = d_dinv[gw];
    float2 o;
    o.x = fmaxf(dv * s0 + bs[2 * lane],     0.f);
    o.y = fmaxf(dv * s1 + bs[2 * lane + 1], 0.f);
    ((float2*)d_hB)[(gw << 5) + lane] = o;
}

// ---------------- mean pool over TP + FC ------------------------------------
__global__ void pool_fc_kernel(const float* __restrict__ fcw,
                               const float* __restrict__ fcb,
                               float* __restrict__ out) {
    __shared__ float m[4][64];
    int b = blockIdx.x, tid = threadIdx.x;
    int f = tid & 63, q = tid >> 6;
    const float* hb = d_hB + (size_t)b * TPP * 64;
    float s = 0.f;
    for (int tp = q; tp < TPP; tp += 4) s += hb[tp * 64 + f];
    m[q][f] = s;
    __syncthreads();
    if (tid < 64) {
        float tot = (m[0][tid] + m[1][tid]) + (m[2][tid] + m[3][tid]);
        m[0][tid] = tot * (1.0f / TPP);
    }
    __syncthreads();
    if (tid < 6) {
        float acc = fcb[tid];
        #pragma unroll
        for (int k = 0; k < 64; k++) acc += m[0][k] * fcw[tid * 64 + k];
        out[b * 6 + tid] = acc;
    }
}

// ---------------- launch -----------------------------------------------------
extern "C" void kernel_launch(void* const* d_in, const int* in_sizes, int n_in,
                              void* d_out, int out_size) {
    const float* x   = (const float*)d_in[0];
    const int*   ei  = (const int*)  d_in[1];
    const float* w1  = (const float*)d_in[2];
    const float* b1  = (const float*)d_in[3];
    const float* w2  = (const float*)d_in[4];
    const float* b2  = (const float*)d_in[5];
    const float* g1w = (const float*)d_in[6];
    const float* g1b = (const float*)d_in[7];
    const float* g2w = (const float*)d_in[8];
    const float* g2b = (const float*)d_in[9];
    const float* fcw = (const float*)d_in[10];
    const float* fcb = (const float*)d_in[11];
    float* out = (float*)d_out;

    // fork: single fused prep kernel on side stream
    cudaEventRecord(g_ev0, 0);
    cudaStreamWaitEvent(g_s2, g_ev0, 0);
    cudaMemsetAsync(g_cnt_addr, 0, sizeof(unsigned), g_s2);
    prep_kernel<<<PREP_BLOCKS, 1024, 0, g_s2>>>(ei, ei + EE);
    cudaEventRecord(g_evScat, g_s2);

    // main stream: conv1 overlaps prep
    conv1_kernel<<<dim3(8, BB), 128>>>(x, w1, b1);
    cudaStreamWaitEvent(0, g_evScat, 0);          // conv2 needs dinv; gathers need CSR
    conv2_kernel<<<dim3(4, BB), 128>>>(w2, b2);

    // fused GCN layers
    gcn1_fused_kernel<<<NN / 16, 256>>>(g1w, g1b);   // 2 nodes/warp
    gcn2_fused_kernel<<<NN / 8, 256>>>(g2w, g2b);    // 1 node/warp

    // pool + fc
    pool_fc_kernel<<<BB, 256>>>(fcw, fcb, out);
}